// round 11
// baseline (speedup 1.0000x reference)
#include <cuda_runtime.h>
#include <cuda_bf16.h>
#include <cstdint>

#define N_NODES 100000
#define N_EDGES 3200000
#define NF      128
#define H1      32
#define H2      16
#define NG      64
#define TN      32                       // nodes per k_xw1 block
#define SCAN_BLOCKS ((N_NODES + 255) / 256)   // 391

// ---------------- scratch (static device globals; no allocation) -------------
__device__ float g_y1 [N_NODES * H1];   // (x@W1)*dis[node], 12.8 MB
__device__ float g_y2 [N_NODES * H2];   // layer2 premult,    6.4 MB
__device__ float g_dis[N_NODES];
__device__ int   g_degi[N_NODES];
__device__ int   g_off [N_NODES];
__device__ int   g_cur [N_NODES];
__device__ int   g_src32[N_EDGES];
__device__ int   g_dst32[N_EDGES];
__device__ int   g_csr [N_EDGES];       // src ids grouped by dst
__device__ int   g_bsum[SCAN_BLOCKS];
__device__ int   g_boff[SCAN_BLOCKS];
__device__ float g_ns  [N_NODES];       // per-node scalar (pre-pool)
__device__ float g_gsum[NG];
__device__ float g_gcnt[NG];

__device__ __forceinline__ int clampi(int v, int hi) {   // [0, hi)
    return v < 0 ? 0 : (v >= hi ? hi - 1 : v);
}

// ---------------- CSR build -------------------------------------------------

__global__ void k_zero() {
    int i = blockIdx.x * 256 + threadIdx.x;
    if (i < N_NODES) g_degi[i] = 0;
    if (i < NG) { g_gsum[i] = 0.f; g_gcnt[i] = 0.f; }
}

// edge_index is INT32. Copy clamped; count in-degree.
__global__ void k_deg(const int* __restrict__ ei) {
    int e = blockIdx.x * 256 + threadIdx.x;
    if (e >= N_EDGES) return;
    int s = clampi(ei[e], N_NODES);
    int d = clampi(ei[N_EDGES + e], N_NODES);
    g_src32[e] = s;
    g_dst32[e] = d;
    atomicAdd(&g_degi[d], 1);
}

__global__ void k_scanA() {            // per-block degree sums
    __shared__ int sm[256];
    int t = threadIdx.x, i = blockIdx.x * 256 + t;
    sm[t] = (i < N_NODES) ? g_degi[i] : 0;
    __syncthreads();
    for (int off = 128; off > 0; off >>= 1) {
        if (t < off) sm[t] += sm[t + off];
        __syncthreads();
    }
    if (t == 0) g_bsum[blockIdx.x] = sm[0];
}

__global__ void k_scanB() {            // serial scan of 391 block sums
    if (threadIdx.x == 0) {
        int acc = 0;
        for (int b = 0; b < SCAN_BLOCKS; b++) { g_boff[b] = acc; acc += g_bsum[b]; }
    }
}

__global__ void k_scanC() {            // per-block exclusive scan -> offsets
    __shared__ int sm[256];
    int t = threadIdx.x, i = blockIdx.x * 256 + t;
    int v = (i < N_NODES) ? g_degi[i] : 0;
    sm[t] = v;
    __syncthreads();
    for (int off = 1; off < 256; off <<= 1) {
        int tv = (t >= off) ? sm[t - off] : 0;
        __syncthreads();
        sm[t] += tv;
        __syncthreads();
    }
    if (i < N_NODES) {
        int o = g_boff[blockIdx.x] + sm[t] - v;
        g_off[i] = o;
        g_cur[i] = o;
        g_dis[i] = rsqrtf((float)(v + 1));        // +1 self loop
    }
}

__global__ void k_fill() {
    int e = blockIdx.x * 256 + threadIdx.x;
    if (e >= N_EDGES) return;
    int d = g_dst32[e];
    int pos = atomicAdd(&g_cur[d], 1);
    g_csr[pos] = g_src32[e];
}

// ---------------- layer 1 GEMM ----------------------------------------------
// y1[node] = (x[node] @ W1) * dis[node]. Block = 32 nodes x 32 cols,
// thread = 4 nodes x 1 col. 33KB smem -> ~7 blocks/SM.
__global__ __launch_bounds__(256) void k_xw1(const float* __restrict__ x,
                                             const float* __restrict__ W1) {
    __shared__ float  W1s[NF * H1];          // 16 KB
    __shared__ float4 rows4[TN][NF / 4];     // 16 KB
    int tid  = threadIdx.x;
    int base = blockIdx.x * TN;

    for (int i = tid; i < NF * H1 / 4; i += 256)
        ((float4*)W1s)[i] = ((const float4*)W1)[i];
    for (int i = tid; i < TN * NF / 4; i += 256) {
        int node = i >> 5, c4 = i & 31;
        int gn = base + node;
        if (gn >= N_NODES) gn = N_NODES - 1;
        ((float4*)rows4)[i] = ((const float4*)(x + (size_t)gn * NF))[c4];
    }
    __syncthreads();

    int ty = tid >> 5, lane = tid & 31;
    float acc[4] = {0.f, 0.f, 0.f, 0.f};

    #pragma unroll 8
    for (int kk = 0; kk < NF / 4; kk++) {
        int k = kk * 4;
        float w0 = W1s[(k + 0) * H1 + lane];
        float w1 = W1s[(k + 1) * H1 + lane];
        float w2 = W1s[(k + 2) * H1 + lane];
        float w3 = W1s[(k + 3) * H1 + lane];
        #pragma unroll
        for (int j = 0; j < 4; j++) {
            float4 r = rows4[ty * 4 + j][kk];
            acc[j] = fmaf(r.x, w0, acc[j]);
            acc[j] = fmaf(r.y, w1, acc[j]);
            acc[j] = fmaf(r.z, w2, acc[j]);
            acc[j] = fmaf(r.w, w3, acc[j]);
        }
    }
    #pragma unroll
    for (int j = 0; j < 4; j++) {
        int gn = base + ty * 4 + j;
        if (gn < N_NODES)
            g_y1[(size_t)gn * H1 + lane] = acc[j] * g_dis[gn];
    }
}

// ---------------- fused gather layer 1 + ReLU + W2 --------------------------
// Warp per dst node; lane = H1 column. Edge ids batch-loaded 32 at a time
// (coalesced) then broadcast by shfl -> independent y1 row loads (high MLP).
__global__ __launch_bounds__(256) void k_gather1(const float* __restrict__ b1,
                                                 const float* __restrict__ W2) {
    __shared__ float W2s[H1 * H2];
    __shared__ float b1s[H1];
    int tid = threadIdx.x;
    for (int i = tid; i < H1 * H2; i += 256) W2s[i] = W2[i];
    if (tid < H1) b1s[tid] = b1[tid];
    __syncthreads();

    int warp = tid >> 5, lane = tid & 31;
    int d = blockIdx.x * 8 + warp;
    if (d >= N_NODES) return;

    float sum = g_y1[d * H1 + lane];                 // self loop (premult)
    int beg = g_off[d], end = beg + g_degi[d];
    for (int base = beg; base < end; base += 32) {
        int cnt = end - base; if (cnt > 32) cnt = 32;
        int my = (lane < cnt) ? g_csr[base + lane] : 0;
        for (int t = 0; t < cnt; t++) {
            int s = __shfl_sync(0xffffffffu, my, t);
            sum += g_y1[s * H1 + lane];
        }
    }
    float dis = g_dis[d];
    float h = fmaxf(fmaf(dis, sum, b1s[lane]), 0.f);

    // o[col] = sum_k h_k * W2[k][col]; halves split the k range.
    int col = lane & 15, half = lane >> 4;
    float o = 0.f;
    #pragma unroll
    for (int k = 0; k < 16; k++) {
        int kk = k + half * 16;
        float hk = __shfl_sync(0xffffffffu, h, kk);
        o = fmaf(hk, W2s[kk * H2 + col], o);
    }
    o += __shfl_xor_sync(0xffffffffu, o, 16);
    if (lane < 16) g_y2[d * H2 + lane] = o * dis;    // premult for layer 2
}

// ---------------- fused gather layer 2 + lin head ---------------------------
// Warp per dst node; lane = (col = lane&15, half = lane>>4): 2 edges in flight.
__global__ __launch_bounds__(256) void k_gather2(const float* __restrict__ b2,
                                                 const float* __restrict__ lw) {
    __shared__ float b2s[H2];
    __shared__ float lws[H2];
    int tid = threadIdx.x;
    if (tid < H2)          b2s[tid] = b2[tid];
    else if (tid < 2 * H2) lws[tid - H2] = lw[tid - H2];
    __syncthreads();

    int warp = tid >> 5, lane = tid & 31;
    int d = blockIdx.x * 8 + warp;
    if (d >= N_NODES) return;

    int col = lane & 15, half = lane >> 4;
    float sum = (half == 0) ? g_y2[d * H2 + col] : 0.f;   // self loop once
    int beg = g_off[d], end = beg + g_degi[d];
    for (int base = beg; base < end; base += 32) {
        int cnt = end - base; if (cnt > 32) cnt = 32;
        int my = (lane < cnt) ? g_csr[base + lane] : 0;
        int tmax = (cnt + 1) >> 1;
        for (int t = 0; t < tmax; t++) {
            int eidx = t * 2 + half;
            int sel = eidx < cnt ? eidx : cnt - 1;
            int s = __shfl_sync(0xffffffffu, my, sel);
            float v = g_y2[s * H2 + col];
            if (eidx < cnt) sum += v;
        }
    }
    sum += __shfl_xor_sync(0xffffffffu, sum, 16);
    float h2 = fmaf(g_dis[d], sum, b2s[col]);
    float p = h2 * lws[col];
    p += __shfl_xor_sync(0xffffffffu, p, 8);
    p += __shfl_xor_sync(0xffffffffu, p, 4);
    p += __shfl_xor_sync(0xffffffffu, p, 2);
    p += __shfl_xor_sync(0xffffffffu, p, 1);
    if (lane == 0) g_ns[d] = p;
}

// ---------------- pooling ----------------------------------------------------
__global__ void k_pool(const int* __restrict__ batch) {
    int i = blockIdx.x * 256 + threadIdx.x;
    bool act = (i < N_NODES);
    float s = 0.f;
    int g = 0;
    if (act) {
        s = g_ns[i];
        g = clampi(batch[i], NG);
    }
    unsigned mask = __ballot_sync(0xffffffffu, act);
    if (!act) return;
    if (mask == 0xffffffffu && __all_sync(0xffffffffu, g == __shfl_sync(0xffffffffu, g, 0))) {
        #pragma unroll
        for (int o = 16; o > 0; o >>= 1) s += __shfl_down_sync(0xffffffffu, s, o);
        if ((threadIdx.x & 31) == 0) {
            atomicAdd(&g_gsum[g], s);
            atomicAdd(&g_gcnt[g], 32.f);
        }
    } else {
        atomicAdd(&g_gsum[g], s);
        atomicAdd(&g_gcnt[g], 1.f);
    }
}

__global__ void k_final(const float* __restrict__ lb, float* __restrict__ out) {
    int g = threadIdx.x;
    if (g < NG) out[g] = g_gsum[g] / fmaxf(g_gcnt[g], 1.f) + lb[0];
}

// ---------------- launch -----------------------------------------------------
extern "C" void kernel_launch(void* const* d_in, const int* in_sizes, int n_in,
                              void* d_out, int out_size) {
    const void* p_by_size[9] = {0,0,0,0,0,0,0,0,0};
    int sixteen_seen = 0;
    const void *p16a = 0, *p16b = 0;
    for (int i = 0; i < n_in; i++) {
        switch (in_sizes[i]) {
            case N_NODES * NF:   p_by_size[0] = d_in[i]; break;  // x
            case 2 * N_EDGES:    p_by_size[1] = d_in[i]; break;  // edge_index
            case N_NODES:        p_by_size[2] = d_in[i]; break;  // batch
            case NF * H1:        p_by_size[3] = d_in[i]; break;  // W1
            case H1:             p_by_size[4] = d_in[i]; break;  // b1
            case H1 * H2:        p_by_size[5] = d_in[i]; break;  // W2
            case H2:             if (sixteen_seen++ == 0) p16a = d_in[i];
                                 else                     p16b = d_in[i];
                                 break;                           // b2 then lin_w
            case 1:              p_by_size[8] = d_in[i]; break;  // lin_b
            default: break;
        }
    }
    p_by_size[6] = p16a;   // b2
    p_by_size[7] = p16b;   // lin_w
    for (int i = 0; i < 9; i++) if (!p_by_size[i] && i < n_in) p_by_size[i] = d_in[i];

    const float* x     = (const float*)p_by_size[0];
    const int*   ei    = (const int*)p_by_size[1];
    const int*   batch = (const int*)p_by_size[2];
    const float* W1    = (const float*)p_by_size[3];
    const float* b1    = (const float*)p_by_size[4];
    const float* W2    = (const float*)p_by_size[5];
    const float* b2    = (const float*)p_by_size[6];
    const float* lw    = (const float*)p_by_size[7];
    const float* lb    = (const float*)p_by_size[8];
    float*       out   = (float*)d_out;

    k_zero    <<<SCAN_BLOCKS, 256>>>();
    k_deg     <<<(N_EDGES + 255) / 256, 256>>>(ei);
    k_scanA   <<<SCAN_BLOCKS, 256>>>();
    k_scanB   <<<1, 32>>>();
    k_scanC   <<<SCAN_BLOCKS, 256>>>();
    k_fill    <<<(N_EDGES + 255) / 256, 256>>>();
    k_xw1     <<<(N_NODES + TN - 1) / TN, 256>>>(x, W1);
    k_gather1 <<<(N_NODES + 7) / 8, 256>>>(b1, W2);
    k_gather2 <<<(N_NODES + 7) / 8, 256>>>(b2, lw);
    k_pool    <<<(N_NODES + 255) / 256, 256>>>(batch);
    k_final   <<<1, 64>>>(lb, out);
}

// round 13
// speedup vs baseline: 1.1652x; 1.1652x over previous
#include <cuda_runtime.h>
#include <cuda_fp16.h>
#include <cstdint>

#define N_NODES 100000
#define N_EDGES 3200000
#define NF      128
#define H1      32
#define H2      16
#define NG      64
#define TN      32                       // nodes per k_xw1 block
#define FULLM   0xffffffffu

// ---------------- scratch (static device globals; no allocation) -------------
__device__ __half2 g_y1h[N_NODES * H1 / 2];  // (x@W1)*dis, fp16, 6.4 MB
__device__ __half2 g_y2h[N_NODES * H2 / 2];  // layer2 premult, fp16, 3.2 MB
__device__ float g_dis[N_NODES];
__device__ int   g_degi[N_NODES];
__device__ int   g_off [N_NODES];
__device__ int   g_cur [N_NODES];
__device__ int   g_src32[N_EDGES];
__device__ int   g_dst32[N_EDGES];
__device__ int   g_csr [N_EDGES];            // src ids grouped by dst
__device__ int   g_ecnt;
__device__ float g_ns  [N_NODES];            // per-node scalar (pre-pool)
__device__ float g_gsum[NG];
__device__ float g_gcnt[NG];

__device__ __forceinline__ int clampi(int v, int hi) {   // [0, hi)
    return v < 0 ? 0 : (v >= hi ? hi - 1 : v);
}

// ---------------- CSR build -------------------------------------------------

__global__ void k_zero() {
    int i = blockIdx.x * 256 + threadIdx.x;
    if (i < N_NODES) g_degi[i] = 0;
    if (i < NG) { g_gsum[i] = 0.f; g_gcnt[i] = 0.f; }
    if (i == 0) g_ecnt = 0;
}

// edge_index is INT32. Copy clamped; count in-degree.
__global__ void k_deg(const int* __restrict__ ei) {
    int e = blockIdx.x * 256 + threadIdx.x;
    if (e >= N_EDGES) return;
    int s = clampi(ei[e], N_NODES);
    int d = clampi(ei[N_EDGES + e], N_NODES);
    g_src32[e] = s;
    g_dst32[e] = d;
    atomicAdd(&g_degi[d], 1);
}

// Order-free offset assignment: warp scan + one atomicAdd per warp.
__global__ void k_off() {
    int i = blockIdx.x * 256 + threadIdx.x;
    int lane = threadIdx.x & 31;
    bool act = (i < N_NODES);
    int deg = act ? g_degi[i] : 0;
    int incl = deg;
    #pragma unroll
    for (int o = 1; o < 32; o <<= 1) {
        int v = __shfl_up_sync(FULLM, incl, o);
        if (lane >= o) incl += v;
    }
    int total = __shfl_sync(FULLM, incl, 31);
    int basev = 0;
    if (lane == 0 && total > 0) basev = atomicAdd(&g_ecnt, total);
    basev = __shfl_sync(FULLM, basev, 0);
    if (act) {
        int o = basev + incl - deg;
        g_off[i] = o;
        g_cur[i] = o;
        g_dis[i] = rsqrtf((float)(deg + 1));     // +1 self loop
    }
}

__global__ void k_fill() {
    int e = blockIdx.x * 256 + threadIdx.x;
    if (e >= N_EDGES) return;
    int d = g_dst32[e];
    int pos = atomicAdd(&g_cur[d], 1);
    g_csr[pos] = g_src32[e];
}

// ---------------- layer 1 GEMM ----------------------------------------------
// y1[node] = (x[node] @ W1) * dis[node], stored fp16. Block = 32 nodes x 32
// cols, thread = 4 nodes x 1 col.
__global__ __launch_bounds__(256) void k_xw1(const float* __restrict__ x,
                                             const float* __restrict__ W1) {
    __shared__ float  W1s[NF * H1];          // 16 KB
    __shared__ float4 rows4[TN][NF / 4];     // 16 KB
    int tid  = threadIdx.x;
    int base = blockIdx.x * TN;

    for (int i = tid; i < NF * H1 / 4; i += 256)
        ((float4*)W1s)[i] = ((const float4*)W1)[i];
    for (int i = tid; i < TN * NF / 4; i += 256) {
        int node = i >> 5, c4 = i & 31;
        int gn = base + node;
        if (gn >= N_NODES) gn = N_NODES - 1;
        ((float4*)rows4)[i] = ((const float4*)(x + (size_t)gn * NF))[c4];
    }
    __syncthreads();

    int ty = tid >> 5, lane = tid & 31;
    float acc[4] = {0.f, 0.f, 0.f, 0.f};

    #pragma unroll 8
    for (int kk = 0; kk < NF / 4; kk++) {
        int k = kk * 4;
        float w0 = W1s[(k + 0) * H1 + lane];
        float w1 = W1s[(k + 1) * H1 + lane];
        float w2 = W1s[(k + 2) * H1 + lane];
        float w3 = W1s[(k + 3) * H1 + lane];
        #pragma unroll
        for (int j = 0; j < 4; j++) {
            float4 r = rows4[ty * 4 + j][kk];
            acc[j] = fmaf(r.x, w0, acc[j]);
            acc[j] = fmaf(r.y, w1, acc[j]);
            acc[j] = fmaf(r.z, w2, acc[j]);
            acc[j] = fmaf(r.w, w3, acc[j]);
        }
    }
    #pragma unroll
    for (int j = 0; j < 4; j++) {
        int gn = base + ty * 4 + j;
        float hi = __shfl_down_sync(FULLM, acc[j], 1);
        if (gn < N_NODES && (lane & 1) == 0) {
            float dis = g_dis[gn];
            g_y1h[gn * (H1 / 2) + (lane >> 1)] =
                __floats2half2_rn(acc[j] * dis, hi * dis);
        }
    }
}

// ---------------- fused gather layer 1 + ReLU + W2 --------------------------
// Warp per dst node. lane = (half = lane>>4 : edge parity, col2 = lane&15 :
// column pair). 2 edges in flight x unroll 4 -> 8 outstanding 4B loads/lane.
__global__ __launch_bounds__(256) void k_gather1(const float* __restrict__ b1,
                                                 const float* __restrict__ W2) {
    __shared__ float W2s[H1 * H2];
    __shared__ float b1s[H1];
    int tid = threadIdx.x;
    for (int i = tid; i < H1 * H2; i += 256) W2s[i] = W2[i];
    if (tid < H1) b1s[tid] = b1[tid];
    __syncthreads();

    int warp = tid >> 5, lane = tid & 31;
    int d = blockIdx.x * 8 + warp;
    if (d >= N_NODES) return;

    int col2 = lane & 15, half = lane >> 4;

    float2 sum;
    if (half == 0) sum = __half22float2(g_y1h[d * 16 + col2]);  // self loop
    else           sum = make_float2(0.f, 0.f);

    int beg = g_off[d], end = beg + g_degi[d];
    for (int base = beg; base < end; base += 32) {
        int cnt = end - base; if (cnt > 32) cnt = 32;
        int my = (lane < cnt) ? g_csr[base + lane] : 0;
        int nFull = cnt >> 1;          // iterations where both halves valid
        int t = 0;
        for (; t + 4 <= nFull; t += 4) {
            int s0 = __shfl_sync(FULLM, my, 2 * (t + 0) + half);
            int s1 = __shfl_sync(FULLM, my, 2 * (t + 1) + half);
            int s2 = __shfl_sync(FULLM, my, 2 * (t + 2) + half);
            int s3 = __shfl_sync(FULLM, my, 2 * (t + 3) + half);
            float2 v0 = __half22float2(g_y1h[s0 * 16 + col2]);
            float2 v1 = __half22float2(g_y1h[s1 * 16 + col2]);
            float2 v2 = __half22float2(g_y1h[s2 * 16 + col2]);
            float2 v3 = __half22float2(g_y1h[s3 * 16 + col2]);
            sum.x += (v0.x + v1.x) + (v2.x + v3.x);
            sum.y += (v0.y + v1.y) + (v2.y + v3.y);
        }
        for (; t < nFull; t++) {
            int s = __shfl_sync(FULLM, my, 2 * t + half);
            float2 v = __half22float2(g_y1h[s * 16 + col2]);
            sum.x += v.x; sum.y += v.y;
        }
        if ((cnt & 1) && half == 0) {
            int s = __shfl_sync(FULLM, my, cnt - 1);
            float2 v = __half22float2(g_y1h[s * 16 + col2]);
            sum.x += v.x; sum.y += v.y;
        } else if (cnt & 1) {
            __shfl_sync(FULLM, my, cnt - 1);    // keep shfl warp-uniform
        }
    }
    sum.x += __shfl_xor_sync(FULLM, sum.x, 16);
    sum.y += __shfl_xor_sync(FULLM, sum.y, 16);

    float dis = g_dis[d];
    float2 h;
    h.x = fmaxf(fmaf(dis, sum.x, b1s[2 * col2 + 0]), 0.f);
    h.y = fmaxf(fmaf(dis, sum.y, b1s[2 * col2 + 1]), 0.f);

    // o[col] = sum_k h_k W2[k][col]; halves split the 16 k-pairs.
    float o = 0.f;
    #pragma unroll
    for (int kp = 0; kp < 8; kp++) {
        int kk = kp + half * 8;                 // k-pair index 0..15
        float hx = __shfl_sync(FULLM, h.x, kk);
        float hy = __shfl_sync(FULLM, h.y, kk);
        o = fmaf(hx, W2s[(2 * kk + 0) * H2 + col2], o);
        o = fmaf(hy, W2s[(2 * kk + 1) * H2 + col2], o);
    }
    o += __shfl_xor_sync(FULLM, o, 16);         // col2 is the output col (0..15)
    float ohi = __shfl_down_sync(FULLM, o, 1);
    if (half == 0 && (col2 & 1) == 0)
        g_y2h[d * 8 + (col2 >> 1)] = __floats2half2_rn(o * dis, ohi * dis);
}

// ---------------- fused gather layer 2 + lin head ---------------------------
// Warp per dst node. lane = (q = lane>>3 : edge slot 0..3, col2 = lane&7).
__global__ __launch_bounds__(256) void k_gather2(const float* __restrict__ b2,
                                                 const float* __restrict__ lw) {
    __shared__ float b2s[H2];
    __shared__ float lws[H2];
    int tid = threadIdx.x;
    if (tid < H2)          b2s[tid] = b2[tid];
    else if (tid < 2 * H2) lws[tid - H2] = lw[tid - H2];
    __syncthreads();

    int warp = tid >> 5, lane = tid & 31;
    int d = blockIdx.x * 8 + warp;
    if (d >= N_NODES) return;

    int col2 = lane & 7, q = lane >> 3;

    float2 sum;
    if (q == 0) sum = __half22float2(g_y2h[d * 8 + col2]);   // self loop
    else        sum = make_float2(0.f, 0.f);

    int beg = g_off[d], end = beg + g_degi[d];
    for (int base = beg; base < end; base += 32) {
        int cnt = end - base; if (cnt > 32) cnt = 32;
        int my = (lane < cnt) ? g_csr[base + lane] : 0;
        int nFull = cnt >> 2;          // iterations where all 4 slots valid
        int t = 0;
        for (; t + 4 <= nFull; t += 4) {
            int s0 = __shfl_sync(FULLM, my, 4 * (t + 0) + q);
            int s1 = __shfl_sync(FULLM, my, 4 * (t + 1) + q);
            int s2 = __shfl_sync(FULLM, my, 4 * (t + 2) + q);
            int s3 = __shfl_sync(FULLM, my, 4 * (t + 3) + q);
            float2 v0 = __half22float2(g_y2h[s0 * 8 + col2]);
            float2 v1 = __half22float2(g_y2h[s1 * 8 + col2]);
            float2 v2 = __half22float2(g_y2h[s2 * 8 + col2]);
            float2 v3 = __half22float2(g_y2h[s3 * 8 + col2]);
            sum.x += (v0.x + v1.x) + (v2.x + v3.x);
            sum.y += (v0.y + v1.y) + (v2.y + v3.y);
        }
        for (; t < nFull; t++) {
            int s = __shfl_sync(FULLM, my, 4 * t + q);
            float2 v = __half22float2(g_y2h[s * 8 + col2]);
            sum.x += v.x; sum.y += v.y;
        }
        int rem = cnt & 3;
        if (rem) {
            int eidx = 4 * nFull + q;
            int sel  = eidx < cnt ? eidx : 0;
            int s = __shfl_sync(FULLM, my, sel);
            if (q < rem) {
                float2 v = __half22float2(g_y2h[s * 8 + col2]);
                sum.x += v.x; sum.y += v.y;
            }
        }
    }
    sum.x += __shfl_xor_sync(FULLM, sum.x, 8);
    sum.y += __shfl_xor_sync(FULLM, sum.y, 8);
    sum.x += __shfl_xor_sync(FULLM, sum.x, 16);
    sum.y += __shfl_xor_sync(FULLM, sum.y, 16);

    float dis = g_dis[d];
    float hx = fmaf(dis, sum.x, b2s[2 * col2 + 0]);
    float hy = fmaf(dis, sum.y, b2s[2 * col2 + 1]);
    float p = hx * lws[2 * col2 + 0] + hy * lws[2 * col2 + 1];
    p += __shfl_xor_sync(FULLM, p, 4);
    p += __shfl_xor_sync(FULLM, p, 2);
    p += __shfl_xor_sync(FULLM, p, 1);
    if (lane == 0) g_ns[d] = p;
}

// ---------------- pooling ----------------------------------------------------
__global__ void k_pool(const int* __restrict__ batch) {
    int i = blockIdx.x * 256 + threadIdx.x;
    bool act = (i < N_NODES);
    float s = 0.f;
    int g = 0;
    if (act) {
        s = g_ns[i];
        g = clampi(batch[i], NG);
    }
    unsigned mask = __ballot_sync(FULLM, act);
    if (!act) return;
    if (mask == FULLM && __all_sync(FULLM, g == __shfl_sync(FULLM, g, 0))) {
        #pragma unroll
        for (int o = 16; o > 0; o >>= 1) s += __shfl_down_sync(FULLM, s, o);
        if ((threadIdx.x & 31) == 0) {
            atomicAdd(&g_gsum[g], s);
            atomicAdd(&g_gcnt[g], 32.f);
        }
    } else {
        atomicAdd(&g_gsum[g], s);
        atomicAdd(&g_gcnt[g], 1.f);
    }
}

__global__ void k_final(const float* __restrict__ lb, float* __restrict__ out) {
    int g = threadIdx.x;
    if (g < NG) out[g] = g_gsum[g] / fmaxf(g_gcnt[g], 1.f) + lb[0];
}

// ---------------- launch -----------------------------------------------------
extern "C" void kernel_launch(void* const* d_in, const int* in_sizes, int n_in,
                              void* d_out, int out_size) {
    const void* p_by_size[9] = {0,0,0,0,0,0,0,0,0};
    int sixteen_seen = 0;
    const void *p16a = 0, *p16b = 0;
    for (int i = 0; i < n_in; i++) {
        switch (in_sizes[i]) {
            case N_NODES * NF:   p_by_size[0] = d_in[i]; break;  // x
            case 2 * N_EDGES:    p_by_size[1] = d_in[i]; break;  // edge_index
            case N_NODES:        p_by_size[2] = d_in[i]; break;  // batch
            case NF * H1:        p_by_size[3] = d_in[i]; break;  // W1
            case H1:             p_by_size[4] = d_in[i]; break;  // b1
            case H1 * H2:        p_by_size[5] = d_in[i]; break;  // W2
            case H2:             if (sixteen_seen++ == 0) p16a = d_in[i];
                                 else                     p16b = d_in[i];
                                 break;                           // b2 then lin_w
            case 1:              p_by_size[8] = d_in[i]; break;  // lin_b
            default: break;
        }
    }
    p_by_size[6] = p16a;   // b2
    p_by_size[7] = p16b;   // lin_w
    for (int i = 0; i < 9; i++) if (!p_by_size[i] && i < n_in) p_by_size[i] = d_in[i];

    const float* x     = (const float*)p_by_size[0];
    const int*   ei    = (const int*)p_by_size[1];
    const int*   batch = (const int*)p_by_size[2];
    const float* W1    = (const float*)p_by_size[3];
    const float* b1    = (const float*)p_by_size[4];
    const float* W2    = (const float*)p_by_size[5];
    const float* b2    = (const float*)p_by_size[6];
    const float* lw    = (const float*)p_by_size[7];
    const float* lb    = (const float*)p_by_size[8];
    float*       out   = (float*)d_out;

    k_zero    <<<(N_NODES + 255) / 256, 256>>>();
    k_deg     <<<(N_EDGES + 255) / 256, 256>>>(ei);
    k_off     <<<(N_NODES + 255) / 256, 256>>>();
    k_fill    <<<(N_EDGES + 255) / 256, 256>>>();
    k_xw1     <<<(N_NODES + TN - 1) / TN, 256>>>(x, W1);
    k_gather1 <<<(N_NODES + 7) / 8, 256>>>(b1, W2);
    k_gather2 <<<(N_NODES + 7) / 8, 256>>>(b2, lw);
    k_pool    <<<(N_NODES + 255) / 256, 256>>>(batch);
    k_final   <<<1, 64>>>(lb, out);
}

// round 15
// speedup vs baseline: 1.2257x; 1.0520x over previous
#include <cuda_runtime.h>
#include <cuda_fp16.h>
#include <cstdint>

#define N_NODES 100000
#define N_EDGES 3200000
#define NF      128
#define H1      32
#define H2      16
#define NG      64
#define TN      32                       // nodes per k_xw1 block
#define FULLM   0xffffffffu

// ---------------- scratch (static device globals; no allocation) -------------
__device__ __half2 g_y1h[N_NODES * H1 / 2];  // (x@W1)*dis, fp16, 6.4 MB
__device__ __half2 g_y2h[N_NODES * H2 / 2];  // layer2 premult, fp16, 3.2 MB
__device__ float g_dis[N_NODES];
__device__ int   g_degi[N_NODES];
__device__ int   g_off [N_NODES];
__device__ unsigned short g_rank[N_EDGES];   // rank of edge within dst bucket
__device__ int   g_csr [N_EDGES];            // src ids grouped by dst
__device__ int   g_ecnt;
__device__ float g_ns  [N_NODES];            // per-node scalar (pre-pool)
__device__ float g_gsum[NG];
__device__ float g_gcnt[NG];

__device__ __forceinline__ int clampi(int v, int hi) {   // [0, hi)
    return v < 0 ? 0 : (v >= hi ? hi - 1 : v);
}

// ---------------- CSR build -------------------------------------------------

__global__ void k_zero() {
    int i = blockIdx.x * 256 + threadIdx.x;
    if (i < N_NODES) g_degi[i] = 0;
    if (i < NG) { g_gsum[i] = 0.f; g_gcnt[i] = 0.f; }
    if (i == 0) g_ecnt = 0;
}

// Count in-degree; the atomic's return value IS the edge's slot rank.
__global__ void k_deg(const int* __restrict__ ei) {
    int e = blockIdx.x * 256 + threadIdx.x;
    if (e >= N_EDGES) return;
    int d = clampi(ei[N_EDGES + e], N_NODES);
    int r = atomicAdd(&g_degi[d], 1);
    g_rank[e] = (unsigned short)r;
}

// Order-free offset assignment: warp scan + one atomicAdd per warp.
__global__ void k_off() {
    int i = blockIdx.x * 256 + threadIdx.x;
    int lane = threadIdx.x & 31;
    bool act = (i < N_NODES);
    int deg = act ? g_degi[i] : 0;
    int incl = deg;
    #pragma unroll
    for (int o = 1; o < 32; o <<= 1) {
        int v = __shfl_up_sync(FULLM, incl, o);
        if (lane >= o) incl += v;
    }
    int total = __shfl_sync(FULLM, incl, 31);
    int basev = 0;
    if (lane == 0 && total > 0) basev = atomicAdd(&g_ecnt, total);
    basev = __shfl_sync(FULLM, basev, 0);
    if (act) {
        g_off[i] = basev + incl - deg;
        g_dis[i] = rsqrtf((float)(deg + 1));     // +1 self loop
    }
}

// Atomic-free fill: position fully determined by off[dst] + rank[edge].
__global__ void k_fill(const int* __restrict__ ei) {
    int e = blockIdx.x * 256 + threadIdx.x;
    if (e >= N_EDGES) return;
    int s = clampi(ei[e], N_NODES);
    int d = clampi(ei[N_EDGES + e], N_NODES);
    int pos = g_off[d] + (int)g_rank[e];
    g_csr[pos] = s;
}

// ---------------- layer 1 GEMM ----------------------------------------------
// y1[node] = (x[node] @ W1) * dis[node], stored fp16. Block = 32 nodes x 32
// cols, thread = 4 nodes x 1 col.
__global__ __launch_bounds__(256) void k_xw1(const float* __restrict__ x,
                                             const float* __restrict__ W1) {
    __shared__ float  W1s[NF * H1];          // 16 KB
    __shared__ float4 rows4[TN][NF / 4];     // 16 KB
    int tid  = threadIdx.x;
    int base = blockIdx.x * TN;

    for (int i = tid; i < NF * H1 / 4; i += 256)
        ((float4*)W1s)[i] = ((const float4*)W1)[i];
    for (int i = tid; i < TN * NF / 4; i += 256) {
        int node = i >> 5, c4 = i & 31;
        int gn = base + node;
        if (gn >= N_NODES) gn = N_NODES - 1;
        ((float4*)rows4)[i] = ((const float4*)(x + (size_t)gn * NF))[c4];
    }
    __syncthreads();

    int ty = tid >> 5, lane = tid & 31;
    float acc[4] = {0.f, 0.f, 0.f, 0.f};

    #pragma unroll 8
    for (int kk = 0; kk < NF / 4; kk++) {
        int k = kk * 4;
        float w0 = W1s[(k + 0) * H1 + lane];
        float w1 = W1s[(k + 1) * H1 + lane];
        float w2 = W1s[(k + 2) * H1 + lane];
        float w3 = W1s[(k + 3) * H1 + lane];
        #pragma unroll
        for (int j = 0; j < 4; j++) {
            float4 r = rows4[ty * 4 + j][kk];
            acc[j] = fmaf(r.x, w0, acc[j]);
            acc[j] = fmaf(r.y, w1, acc[j]);
            acc[j] = fmaf(r.z, w2, acc[j]);
            acc[j] = fmaf(r.w, w3, acc[j]);
        }
    }
    #pragma unroll
    for (int j = 0; j < 4; j++) {
        int gn = base + ty * 4 + j;
        float hi = __shfl_down_sync(FULLM, acc[j], 1);
        if (gn < N_NODES && (lane & 1) == 0) {
            float dis = g_dis[gn];
            g_y1h[gn * (H1 / 2) + (lane >> 1)] =
                __floats2half2_rn(acc[j] * dis, hi * dis);
        }
    }
}

// ---------------- fused gather layer 1 + ReLU + W2 --------------------------
// Warp per dst node. lane = (half = lane>>4 : edge parity, col2 = lane&15 :
// column pair). 2 edges in flight x unroll 4 -> 8 outstanding loads/lane.
__global__ __launch_bounds__(256) void k_gather1(const float* __restrict__ b1,
                                                 const float* __restrict__ W2) {
    __shared__ float W2s[H1 * H2];
    __shared__ float b1s[H1];
    int tid = threadIdx.x;
    for (int i = tid; i < H1 * H2; i += 256) W2s[i] = W2[i];
    if (tid < H1) b1s[tid] = b1[tid];
    __syncthreads();

    int warp = tid >> 5, lane = tid & 31;
    int d = blockIdx.x * 8 + warp;
    if (d >= N_NODES) return;

    int col2 = lane & 15, half = lane >> 4;

    float2 sum;
    if (half == 0) sum = __half22float2(g_y1h[d * 16 + col2]);  // self loop
    else           sum = make_float2(0.f, 0.f);

    int beg = g_off[d], end = beg + g_degi[d];
    for (int base = beg; base < end; base += 32) {
        int cnt = end - base; if (cnt > 32) cnt = 32;
        int my = (lane < cnt) ? g_csr[base + lane] : 0;
        int nFull = cnt >> 1;          // iterations where both halves valid
        int t = 0;
        for (; t + 4 <= nFull; t += 4) {
            int s0 = __shfl_sync(FULLM, my, 2 * (t + 0) + half);
            int s1 = __shfl_sync(FULLM, my, 2 * (t + 1) + half);
            int s2 = __shfl_sync(FULLM, my, 2 * (t + 2) + half);
            int s3 = __shfl_sync(FULLM, my, 2 * (t + 3) + half);
            float2 v0 = __half22float2(g_y1h[s0 * 16 + col2]);
            float2 v1 = __half22float2(g_y1h[s1 * 16 + col2]);
            float2 v2 = __half22float2(g_y1h[s2 * 16 + col2]);
            float2 v3 = __half22float2(g_y1h[s3 * 16 + col2]);
            sum.x += (v0.x + v1.x) + (v2.x + v3.x);
            sum.y += (v0.y + v1.y) + (v2.y + v3.y);
        }
        for (; t < nFull; t++) {
            int s = __shfl_sync(FULLM, my, 2 * t + half);
            float2 v = __half22float2(g_y1h[s * 16 + col2]);
            sum.x += v.x; sum.y += v.y;
        }
        if ((cnt & 1) && half == 0) {
            int s = __shfl_sync(FULLM, my, cnt - 1);
            float2 v = __half22float2(g_y1h[s * 16 + col2]);
            sum.x += v.x; sum.y += v.y;
        } else if (cnt & 1) {
            __shfl_sync(FULLM, my, cnt - 1);    // keep shfl warp-uniform
        }
    }
    sum.x += __shfl_xor_sync(FULLM, sum.x, 16);
    sum.y += __shfl_xor_sync(FULLM, sum.y, 16);

    float dis = g_dis[d];
    float2 h;
    h.x = fmaxf(fmaf(dis, sum.x, b1s[2 * col2 + 0]), 0.f);
    h.y = fmaxf(fmaf(dis, sum.y, b1s[2 * col2 + 1]), 0.f);

    // o[col] = sum_k h_k W2[k][col]; halves split the 16 k-pairs.
    float o = 0.f;
    #pragma unroll
    for (int kp = 0; kp < 8; kp++) {
        int kk = kp + half * 8;                 // k-pair index 0..15
        float hx = __shfl_sync(FULLM, h.x, kk);
        float hy = __shfl_sync(FULLM, h.y, kk);
        o = fmaf(hx, W2s[(2 * kk + 0) * H2 + col2], o);
        o = fmaf(hy, W2s[(2 * kk + 1) * H2 + col2], o);
    }
    o += __shfl_xor_sync(FULLM, o, 16);         // col2 is the output col (0..15)
    float ohi = __shfl_down_sync(FULLM, o, 1);
    if (half == 0 && (col2 & 1) == 0)
        g_y2h[d * 8 + (col2 >> 1)] = __floats2half2_rn(o * dis, ohi * dis);
}

// ---------------- fused gather layer 2 + lin head ---------------------------
// Warp per dst node. lane = (q = lane>>3 : edge slot 0..3, col2 = lane&7).
__global__ __launch_bounds__(256) void k_gather2(const float* __restrict__ b2,
                                                 const float* __restrict__ lw) {
    __shared__ float b2s[H2];
    __shared__ float lws[H2];
    int tid = threadIdx.x;
    if (tid < H2)          b2s[tid] = b2[tid];
    else if (tid < 2 * H2) lws[tid - H2] = lw[tid - H2];
    __syncthreads();

    int warp = tid >> 5, lane = tid & 31;
    int d = blockIdx.x * 8 + warp;
    if (d >= N_NODES) return;

    int col2 = lane & 7, q = lane >> 3;

    float2 sum;
    if (q == 0) sum = __half22float2(g_y2h[d * 8 + col2]);   // self loop
    else        sum = make_float2(0.f, 0.f);

    int beg = g_off[d], end = beg + g_degi[d];
    for (int base = beg; base < end; base += 32) {
        int cnt = end - base; if (cnt > 32) cnt = 32;
        int my = (lane < cnt) ? g_csr[base + lane] : 0;
        int nFull = cnt >> 2;          // iterations where all 4 slots valid
        int t = 0;
        for (; t + 4 <= nFull; t += 4) {
            int s0 = __shfl_sync(FULLM, my, 4 * (t + 0) + q);
            int s1 = __shfl_sync(FULLM, my, 4 * (t + 1) + q);
            int s2 = __shfl_sync(FULLM, my, 4 * (t + 2) + q);
            int s3 = __shfl_sync(FULLM, my, 4 * (t + 3) + q);
            float2 v0 = __half22float2(g_y2h[s0 * 8 + col2]);
            float2 v1 = __half22float2(g_y2h[s1 * 8 + col2]);
            float2 v2 = __half22float2(g_y2h[s2 * 8 + col2]);
            float2 v3 = __half22float2(g_y2h[s3 * 8 + col2]);
            sum.x += (v0.x + v1.x) + (v2.x + v3.x);
            sum.y += (v0.y + v1.y) + (v2.y + v3.y);
        }
        for (; t < nFull; t++) {
            int s = __shfl_sync(FULLM, my, 4 * t + q);
            float2 v = __half22float2(g_y2h[s * 8 + col2]);
            sum.x += v.x; sum.y += v.y;
        }
        int rem = cnt & 3;
        if (rem) {
            int eidx = 4 * nFull + q;
            int sel  = eidx < cnt ? eidx : 0;
            int s = __shfl_sync(FULLM, my, sel);
            if (q < rem) {
                float2 v = __half22float2(g_y2h[s * 8 + col2]);
                sum.x += v.x; sum.y += v.y;
            }
        }
    }
    sum.x += __shfl_xor_sync(FULLM, sum.x, 8);
    sum.y += __shfl_xor_sync(FULLM, sum.y, 8);
    sum.x += __shfl_xor_sync(FULLM, sum.x, 16);
    sum.y += __shfl_xor_sync(FULLM, sum.y, 16);

    float dis = g_dis[d];
    float hx = fmaf(dis, sum.x, b2s[2 * col2 + 0]);
    float hy = fmaf(dis, sum.y, b2s[2 * col2 + 1]);
    float p = hx * lws[2 * col2 + 0] + hy * lws[2 * col2 + 1];
    p += __shfl_xor_sync(FULLM, p, 4);
    p += __shfl_xor_sync(FULLM, p, 2);
    p += __shfl_xor_sync(FULLM, p, 1);
    if (lane == 0) g_ns[d] = p;
}

// ---------------- pooling ----------------------------------------------------
__global__ void k_pool(const int* __restrict__ batch) {
    int i = blockIdx.x * 256 + threadIdx.x;
    bool act = (i < N_NODES);
    float s = 0.f;
    int g = 0;
    if (act) {
        s = g_ns[i];
        g = clampi(batch[i], NG);
    }
    unsigned mask = __ballot_sync(FULLM, act);
    if (!act) return;
    if (mask == FULLM && __all_sync(FULLM, g == __shfl_sync(FULLM, g, 0))) {
        #pragma unroll
        for (int o = 16; o > 0; o >>= 1) s += __shfl_down_sync(FULLM, s, o);
        if ((threadIdx.x & 31) == 0) {
            atomicAdd(&g_gsum[g], s);
            atomicAdd(&g_gcnt[g], 32.f);
        }
    } else {
        atomicAdd(&g_gsum[g], s);
        atomicAdd(&g_gcnt[g], 1.f);
    }
}

__global__ void k_final(const float* __restrict__ lb, float* __restrict__ out) {
    int g = threadIdx.x;
    if (g < NG) out[g] = g_gsum[g] / fmaxf(g_gcnt[g], 1.f) + lb[0];
}

// ---------------- launch -----------------------------------------------------
extern "C" void kernel_launch(void* const* d_in, const int* in_sizes, int n_in,
                              void* d_out, int out_size) {
    const void* p_by_size[9] = {0,0,0,0,0,0,0,0,0};
    int sixteen_seen = 0;
    const void *p16a = 0, *p16b = 0;
    for (int i = 0; i < n_in; i++) {
        switch (in_sizes[i]) {
            case N_NODES * NF:   p_by_size[0] = d_in[i]; break;  // x
            case 2 * N_EDGES:    p_by_size[1] = d_in[i]; break;  // edge_index
            case N_NODES:        p_by_size[2] = d_in[i]; break;  // batch
            case NF * H1:        p_by_size[3] = d_in[i]; break;  // W1
            case H1:             p_by_size[4] = d_in[i]; break;  // b1
            case H1 * H2:        p_by_size[5] = d_in[i]; break;  // W2
            case H2:             if (sixteen_seen++ == 0) p16a = d_in[i];
                                 else                     p16b = d_in[i];
                                 break;                           // b2 then lin_w
            case 1:              p_by_size[8] = d_in[i]; break;  // lin_b
            default: break;
        }
    }
    p_by_size[6] = p16a;   // b2
    p_by_size[7] = p16b;   // lin_w
    for (int i = 0; i < 9; i++) if (!p_by_size[i] && i < n_in) p_by_size[i] = d_in[i];

    const float* x     = (const float*)p_by_size[0];
    const int*   ei    = (const int*)p_by_size[1];
    const int*   batch = (const int*)p_by_size[2];
    const float* W1    = (const float*)p_by_size[3];
    const float* b1    = (const float*)p_by_size[4];
    const float* W2    = (const float*)p_by_size[5];
    const float* b2    = (const float*)p_by_size[6];
    const float* lw    = (const float*)p_by_size[7];
    const float* lb    = (const float*)p_by_size[8];
    float*       out   = (float*)d_out;

    k_zero    <<<(N_NODES + 255) / 256, 256>>>();
    k_deg     <<<(N_EDGES + 255) / 256, 256>>>(ei);
    k_off     <<<(N_NODES + 255) / 256, 256>>>();
    k_fill    <<<(N_EDGES + 255) / 256, 256>>>(ei);
    k_xw1     <<<(N_NODES + TN - 1) / TN, 256>>>(x, W1);
    k_gather1 <<<(N_NODES + 7) / 8, 256>>>(b1, W2);
    k_gather2 <<<(N_NODES + 7) / 8, 256>>>(b2, lw);
    k_pool    <<<(N_NODES + 255) / 256, 256>>>(batch);
    k_final   <<<1, 64>>>(lb, out);
}